// round 14
// baseline (speedup 1.0000x reference)
#include <cuda_runtime.h>
#include <cuda_fp16.h>

#define MAX_EDGES 3200000
#define MAX_NODES 100000
#define EPS 1e-8f

// Scratch (device globals -- no allocation allowed)
__device__ float g_w[MAX_EDGES];
__device__ float g_rowsum[MAX_NODES];
__device__ __align__(16) __half g_emb1h[MAX_NODES * 16];
__device__ __align__(16) __half g_emb2h[MAX_NODES * 16];

// Prep: one thread per PAIR of float4 (32B read -> one 16B fp16 store),
// plus rowsum zeroing. n2 = n_nodes*2 pairs per table.
//   i in [0, n2):        emb1 pair i  -> g_emb1h uint4 i
//   i in [n2, 2*n2):     emb2 pair    -> g_emb2h
//   i in [2*n2, +nodes): zero rowsum
__global__ void prep_kernel(const float4* __restrict__ emb1,
                            const float4* __restrict__ emb2,
                            int n_nodes) {
    int n2 = n_nodes * 2;
    int i = blockIdx.x * blockDim.x + threadIdx.x;
    if (i < 2 * n2) {
        bool first = (i < n2);
        int p = first ? i : i - n2;
        const float4* sp = (first ? emb1 : emb2) + (size_t)p * 2;
        float4 v0 = __ldg(sp + 0);
        float4 v1 = __ldg(sp + 1);
        __half2 h0 = __floats2half2_rn(v0.x, v0.y);
        __half2 h1 = __floats2half2_rn(v0.z, v0.w);
        __half2 h2 = __floats2half2_rn(v1.x, v1.y);
        __half2 h3 = __floats2half2_rn(v1.z, v1.w);
        uint4 u = make_uint4(*(unsigned*)&h0, *(unsigned*)&h1,
                             *(unsigned*)&h2, *(unsigned*)&h3);
        if (first) ((uint4*)g_emb1h)[p] = u;
        else       ((uint4*)g_emb2h)[p] = u;
    } else if (i < 2 * n2 + n_nodes) {
        g_rowsum[i - 2 * n2] = 0.0f;
    }
}

__device__ __forceinline__ float dot8h(uint4 a, uint4 b) {
    const __half2* ah = (const __half2*)&a;
    const __half2* bh = (const __half2*)&b;
    float acc = 0.0f;
#pragma unroll
    for (int k = 0; k < 4; k++) {
        float2 fa = __half22float2(ah[k]);
        float2 fb = __half22float2(bh[k]);
        acc = fmaf(fa.x, fb.x, acc);
        acc = fmaf(fa.y, fb.y, acc);
    }
    return acc;
}

// Pass 1: 2 lanes per edge; each lane loads one 16B half of both 32B fp16
// rows (pair lanes coalesce to one wavefront per row touched), pair shfl
// reduce; even lane does sigmoid + store + rowsum REDG.
__global__ void edge_score_kernel(const int* __restrict__ src,
                                  const int* __restrict__ dst,
                                  int n_edges) {
    int tid = blockIdx.x * blockDim.x + threadIdx.x;
    int e = tid >> 1;
    int half_sel = tid & 1;
    if (e >= n_edges) return;

    int s = src[e];
    int d = dst[e];

    uint4 av = *((const uint4*)(g_emb1h + (size_t)s * 16) + half_sel);
    uint4 bv = *((const uint4*)(g_emb2h + (size_t)d * 16) + half_sel);

    float acc = dot8h(av, bv);
    acc += __shfl_xor_sync(0xffffffffu, acc, 1);

    if (half_sel == 0) {
        float w = __frcp_rn(1.0f + __expf(-acc));
        g_w[e] = w;
        atomicAdd(&g_rowsum[s], w);
    }
}

// Pass 2: normalize, 4 edges per thread; streaming store for out (never
// re-read -> keep L2 for src/w/rowsum/emb).
__global__ void normalize_kernel(const int4* __restrict__ src4,
                                 float4* __restrict__ out4,
                                 int n_quads) {
    int i = blockIdx.x * blockDim.x + threadIdx.x;
    if (i >= n_quads) return;
    int4 s = src4[i];
    float4 w = ((const float4*)g_w)[i];
    float4 o;
    o.x = w.x / (g_rowsum[s.x] + EPS);
    o.y = w.y / (g_rowsum[s.y] + EPS);
    o.z = w.z / (g_rowsum[s.z] + EPS);
    o.w = w.w / (g_rowsum[s.w] + EPS);
    __stcs(out4 + i, o);
}

// Tail (n_edges not divisible by 4)
__global__ void normalize_tail_kernel(const int* __restrict__ src,
                                      float* __restrict__ out,
                                      int start, int n_edges) {
    int e = start + blockIdx.x * blockDim.x + threadIdx.x;
    if (e >= n_edges) return;
    out[e] = g_w[e] / (g_rowsum[src[e]] + EPS);
}

extern "C" void kernel_launch(void* const* d_in, const int* in_sizes, int n_in,
                              void* d_out, int out_size) {
    const int*    src  = (const int*)d_in[0];
    const int*    dst  = (const int*)d_in[1];
    const float4* emb1 = (const float4*)d_in[2];
    const float4* emb2 = (const float4*)d_in[3];
    float*        out  = (float*)d_out;

    int n_edges = in_sizes[0];
    int n_nodes = in_sizes[2] / 16;

    const int T = 256;

    int prep_items = 4 * n_nodes + n_nodes;  // 2*n2 + n_nodes
    prep_kernel<<<(prep_items + T - 1) / T, T>>>(emb1, emb2, n_nodes);

    int score_threads = 2 * n_edges;
    edge_score_kernel<<<(score_threads + T - 1) / T, T>>>(src, dst, n_edges);

    int n_quads = n_edges / 4;
    if (n_quads > 0)
        normalize_kernel<<<(n_quads + T - 1) / T, T>>>((const int4*)src,
                                                       (float4*)out, n_quads);
    int tail_start = n_quads * 4;
    int tail = n_edges - tail_start;
    if (tail > 0)
        normalize_tail_kernel<<<1, 64>>>(src, out, tail_start, n_edges);
}